// round 4
// baseline (speedup 1.0000x reference)
#include <cuda_runtime.h>
#include <cuda_bf16.h>
#include <cstdint>

#define BB 65536
#define XX 362
#define GS 19
#define TM 128

// ---- weight image (per action,chunk): B2 [128n][120k] hi/lo, B3 [128n][136k] hi/lo ----
#define IMG_B2 0
#define IMG_B2_BYTES 61440
#define IMG_B3 61440
#define IMG_B3_BYTES 69632
#define IMGSZ 131072

// ---- smem layout (bytes) ----
#define OFF_WBUF 0
#define OFF_H1   69632
#define OFF_H2   131072
#define OFF_ATT  200704
#define OFF_W1   204800
#define OFF_B1   207200
#define OFF_B2   207600
#define OFF_B3   209648
#define OFF_W4   210096
#define OFF_B4   213680
#define OFF_SID  213712
#define SMEM_BYTES 214240

// ---- device scratch ----
__device__ float g_att[BB * 6];
__device__ int   g_idx[BB * 6];
__device__ float g_pred[BB * 6];
__device__ int   g_list[3][BB];
__device__ int   g_count[3];
__device__ __align__(16) unsigned char g_wimg[12 * IMGSZ];

__device__ __forceinline__ uint32_t pack2(float e, float o) {
    __nv_bfloat162 t = __floats2bfloat162_rn(e, o);
    return *reinterpret_cast<uint32_t*>(&t);
}
__device__ __forceinline__ void mma16816(float* c, const uint32_t* a, uint32_t b0, uint32_t b1) {
    asm volatile("mma.sync.aligned.m16n8k16.row.col.f32.bf16.bf16.f32 "
                 "{%0,%1,%2,%3}, {%4,%5,%6,%7}, {%8,%9}, {%0,%1,%2,%3};"
                 : "+f"(c[0]), "+f"(c[1]), "+f"(c[2]), "+f"(c[3])
                 : "r"(a[0]), "r"(a[1]), "r"(a[2]), "r"(a[3]), "r"(b0), "r"(b1));
}

// ================= small kernels =================
__global__ void k_reset() {
    if (threadIdx.x < 3) g_count[threadIdx.x] = 0;
}

// Pre-convert W2^T / W3^T to bf16 hi/lo padded [N][K] images.
__global__ void k_prepw(const float* __restrict__ W2, const float* __restrict__ W3) {
    int img = blockIdx.x;           // a*4 + c
    int a = img >> 2, c = img & 3;
    unsigned char* base = g_wimg + (size_t)img * IMGSZ;
    __nv_bfloat16* b2h = (__nv_bfloat16*)(base + IMG_B2);
    __nv_bfloat16* b2l = b2h + 15360;
    __nv_bfloat16* b3h = (__nv_bfloat16*)(base + IMG_B3);
    __nv_bfloat16* b3l = b3h + 17408;
    for (int p = threadIdx.x; p < 128 * 120; p += blockDim.x) {
        int n = p / 120, k = p % 120;
        int gn = c * 128 + n;
        float v = (k < 100 && gn < 400) ? W2[(a * 100 + k) * 400 + gn] : 0.f;
        __nv_bfloat16 h = __float2bfloat16(v);
        b2h[p] = h;
        b2l[p] = __float2bfloat16(v - __bfloat162float(h));
    }
    for (int p = threadIdx.x; p < 128 * 136; p += blockDim.x) {
        int n = p / 136, k = p % 136;
        int gk = c * 128 + k;
        float v = (n < 100 && k < 128 && gk < 400) ? W3[(a * 400 + gk) * 100 + n] : 0.f;
        __nv_bfloat16 h = __float2bfloat16(v);
        b3h[p] = h;
        b3l[p] = __float2bfloat16(v - __bfloat162float(h));
    }
}

// One warp per sample: argmax, row copy, gather att, bucket by action.
__global__ void k_prep(const float* __restrict__ x, const int* __restrict__ act,
                       float* __restrict__ out) {
    int s = (blockIdx.x * blockDim.x + threadIdx.x) >> 5;
    int lane = threadIdx.x & 31;
    if (s >= BB) return;
    const float* row = x + (size_t)s * XX;
    float* orow = out + (size_t)s * XX;

    float best = -3.4e38f;
    int bidx = XX;
    for (int i = lane; i < XX; i += 32) {
        float v = row[i];
        orow[i] = v;
        if (v > best) { best = v; bidx = i; }
    }
#pragma unroll
    for (int off = 16; off; off >>= 1) {
        float ov = __shfl_down_sync(0xffffffffu, best, off);
        int oi = __shfl_down_sync(0xffffffffu, bidx, off);
        if (ov > best || (ov == best && oi < bidx)) { best = ov; bidx = oi; }
    }
    bidx = __shfl_sync(0xffffffffu, bidx, 0);

    if (lane < 6) {
        int id;
        if (lane == 0) id = 0;
        else if (lane == 1) id = bidx;
        else {
            int d = (lane == 2) ? -GS : (lane == 3) ? GS : (lane == 4) ? -1 : 1;
            id = bidx + d;
            id = id < 1 ? 1 : (id > XX - 1 ? XX - 1 : id);
        }
        g_idx[s * 6 + lane] = id;
        g_att[s * 6 + lane] = row[id];
    }
    if (lane == 0) {
        int a = act[s];
        int pos = atomicAdd(&g_count[a], 1);
        g_list[a][pos] = s;
    }
}

// ================= mma.sync MLP (512 threads, 4x4 warp grid) =================
__global__ __launch_bounds__(512)
void k_mlp(const float* __restrict__ W1, const float* __restrict__ b1,
           const float* __restrict__ b2, const float* __restrict__ b3,
           const float* __restrict__ W4, const float* __restrict__ b4) {
    extern __shared__ char sm[];
    int a = blockIdx.y;
    int count = g_count[a];
    int m0 = blockIdx.x * TM;
    if (m0 >= count) return;
    int M = min(TM, count - m0);
    int tid = threadIdx.x;
    int wid = tid >> 5, lane = tid & 31;
    int grp = lane >> 2, qid = lane & 3;
    int wm = wid >> 2, wn = wid & 3;

    int*   sid  = (int*)(sm + OFF_SID);
    float* attS = (float*)(sm + OFF_ATT);
    float* w1S  = (float*)(sm + OFF_W1);
    float* b1S  = (float*)(sm + OFF_B1);
    float* b2S  = (float*)(sm + OFF_B2);
    float* b3S  = (float*)(sm + OFF_B3);
    float* w4S  = (float*)(sm + OFF_W4);
    float* b4S  = (float*)(sm + OFF_B4);

    uint32_t* wbH = (uint32_t*)(sm + OFF_WBUF);      // B2: stride 60 words; B3: stride 68
    uint32_t* h1H = (uint32_t*)(sm + OFF_H1);        // [128][60w] bf16x2
    uint32_t* h1L = h1H + 7680;
    uint32_t* h2H = (uint32_t*)(sm + OFF_H2);        // [128][68w]
    uint32_t* h2L = h2H + 8704;

    // ---- stage misc ----
    if (tid < TM) sid[tid] = (tid < M) ? g_list[a][m0 + tid] : 0;
    for (int p = tid; p < 600; p += 512) w1S[p] = W1[a * 600 + p];
    if (tid < 100) b1S[tid] = b1[a * 100 + tid];
    if (tid < 512) b2S[tid] = (tid < 400) ? b2[a * 400 + tid] : 0.f;
    if (tid < 112) b3S[tid] = (tid < 100) ? b3[a * 100 + tid] : 0.f;
    for (int p = tid; p < 896; p += 512) {
        int k = p >> 3, o = p & 7;
        w4S[p] = (k < 100 && o < 6) ? W4[(a * 100 + k) * 6 + o] : 0.f;
    }
    if (tid < 8) b4S[tid] = (tid < 6) ? b4[a * 6 + tid] : 0.f;
    __syncthreads();
    for (int p = tid; p < 1024; p += 512) {
        int m = p >> 3, q = p & 7;
        attS[p] = (m < M && q < 8 && q < 6) ? g_att[sid[m] * 6 + q] : 0.f;
    }
    __syncthreads();

    // ---- layer1 (scalar): h1 = relu(att@W1+b1), bf16 hi/lo, cols 0..111 (pad 0) ----
    {
        int m = tid >> 2;
        int i0 = (tid & 3) * 28;
        float at[6];
#pragma unroll
        for (int q = 0; q < 6; q++) at[q] = attS[m * 8 + q];
        __nv_bfloat16* hh = (__nv_bfloat16*)h1H;
        __nv_bfloat16* hl = (__nv_bfloat16*)h1L;
#pragma unroll 4
        for (int ii = 0; ii < 28; ii++) {
            int i = i0 + ii;
            float v = 0.f;
            if (i < 100) {
                v = b1S[i];
#pragma unroll
                for (int q = 0; q < 6; q++) v += at[q] * w1S[q * 100 + i];
                v = fmaxf(v, 0.f);
            }
            __nv_bfloat16 h = __float2bfloat16(v);
            hh[m * 120 + i] = h;
            hl[m * 120 + i] = __float2bfloat16(v - __bfloat162float(h));
        }
    }

    const unsigned char* img = g_wimg + (size_t)(a * 4) * IMGSZ;
    float acc3[2][4][4];
#pragma unroll
    for (int mt = 0; mt < 2; mt++)
#pragma unroll
        for (int nt = 0; nt < 4; nt++)
#pragma unroll
            for (int e = 0; e < 4; e++) acc3[mt][nt][e] = 0.f;

    for (int c = 0; c < 4; c++) {
        __syncthreads();   // h1 ready (c=0) / prev chunk readers done
        {   // stage W2 chunk (hi+lo contiguous)
            const uint4* src = (const uint4*)(img + (size_t)c * IMGSZ + IMG_B2);
            uint4* dst = (uint4*)(sm + OFF_WBUF);
            for (int p = tid; p < IMG_B2_BYTES / 16; p += 512) dst[p] = src[p];
        }
        __syncthreads();

        // ---- layer2 chunk: C[128x128] = h1 @ W2c, warp tile 32x32 ----
        float acc2[2][4][4];
#pragma unroll
        for (int mt = 0; mt < 2; mt++)
#pragma unroll
            for (int nt = 0; nt < 4; nt++)
#pragma unroll
                for (int e = 0; e < 4; e++) acc2[mt][nt][e] = 0.f;

        uint32_t* w2L = wbH + 7680;
#pragma unroll
        for (int pass = 0; pass < 3; pass++) {
            const uint32_t* Aw = (pass == 2) ? h1L : h1H;
            const uint32_t* Bw = (pass == 1) ? w2L : wbH;
#pragma unroll
            for (int kk = 0; kk < 7; kk++) {
                uint32_t af[2][4];
#pragma unroll
                for (int mt = 0; mt < 2; mt++) {
                    int r = wm * 32 + mt * 16 + grp;
                    af[mt][0] = Aw[r * 60 + kk * 8 + qid];
                    af[mt][1] = Aw[(r + 8) * 60 + kk * 8 + qid];
                    af[mt][2] = Aw[r * 60 + kk * 8 + 4 + qid];
                    af[mt][3] = Aw[(r + 8) * 60 + kk * 8 + 4 + qid];
                }
#pragma unroll
                for (int nt = 0; nt < 4; nt++) {
                    int n = wn * 32 + nt * 8 + grp;
                    uint32_t b0 = Bw[n * 60 + kk * 8 + qid];
                    uint32_t bq = Bw[n * 60 + kk * 8 + 4 + qid];
                    mma16816(acc2[0][nt], af[0], b0, bq);
                    mma16816(acc2[1][nt], af[1], b0, bq);
                }
            }
        }
        // epilogue: h2 = relu(C + b2), bf16 hi/lo
#pragma unroll
        for (int mt = 0; mt < 2; mt++) {
            int r = wm * 32 + mt * 16 + grp;
#pragma unroll
            for (int nt = 0; nt < 4; nt++) {
                int cn = wn * 32 + nt * 8 + qid * 2;
                float bb0 = b2S[c * 128 + cn], bb1 = b2S[c * 128 + cn + 1];
                float v00 = fmaxf(acc2[mt][nt][0] + bb0, 0.f);
                float v01 = fmaxf(acc2[mt][nt][1] + bb1, 0.f);
                float v10 = fmaxf(acc2[mt][nt][2] + bb0, 0.f);
                float v11 = fmaxf(acc2[mt][nt][3] + bb1, 0.f);
                float h00 = __bfloat162float(__float2bfloat16(v00));
                float h01 = __bfloat162float(__float2bfloat16(v01));
                float h10 = __bfloat162float(__float2bfloat16(v10));
                float h11 = __bfloat162float(__float2bfloat16(v11));
                h2H[r * 68 + cn / 2]       = pack2(h00, h01);
                h2L[r * 68 + cn / 2]       = pack2(v00 - h00, v01 - h01);
                h2H[(r + 8) * 68 + cn / 2] = pack2(h10, h11);
                h2L[(r + 8) * 68 + cn / 2] = pack2(v10 - h10, v11 - h11);
            }
        }
        __syncthreads();   // all h2 written, W buffer reads done
        {   // stage W3 chunk
            const uint4* src = (const uint4*)(img + (size_t)c * IMGSZ + IMG_B3);
            uint4* dst = (uint4*)(sm + OFF_WBUF);
            for (int p = tid; p < IMG_B3_BYTES / 16; p += 512) dst[p] = src[p];
        }
        __syncthreads();

        // ---- layer3 partial: acc3 += h2c @ W3c (N rows 112..127 are zero pad) ----
        uint32_t* w3L = wbH + 8704;
#pragma unroll
        for (int pass = 0; pass < 3; pass++) {
            const uint32_t* Aw = (pass == 2) ? h2L : h2H;
            const uint32_t* Bw = (pass == 1) ? w3L : wbH;
#pragma unroll
            for (int kk = 0; kk < 8; kk++) {
                uint32_t af[2][4];
#pragma unroll
                for (int mt = 0; mt < 2; mt++) {
                    int r = wm * 32 + mt * 16 + grp;
                    af[mt][0] = Aw[r * 68 + kk * 8 + qid];
                    af[mt][1] = Aw[(r + 8) * 68 + kk * 8 + qid];
                    af[mt][2] = Aw[r * 68 + kk * 8 + 4 + qid];
                    af[mt][3] = Aw[(r + 8) * 68 + kk * 8 + 4 + qid];
                }
#pragma unroll
                for (int nt = 0; nt < 4; nt++) {
                    int n = wn * 32 + nt * 8 + grp;
                    uint32_t b0 = Bw[n * 68 + kk * 8 + qid];
                    uint32_t bq = Bw[n * 68 + kk * 8 + 4 + qid];
                    mma16816(acc3[0][nt], af[0], b0, bq);
                    mma16816(acc3[1][nt], af[1], b0, bq);
                }
            }
        }
    }
    __syncthreads();   // reuse H1 region as h3

    // ---- epilogue3: h3 = relu(acc3 + b3) -> fp32 smem [128][116], cols < 112 ----
    float* h3S = (float*)(sm + OFF_H1);
#pragma unroll
    for (int mt = 0; mt < 2; mt++) {
        int r = wm * 32 + mt * 16 + grp;
#pragma unroll
        for (int nt = 0; nt < 4; nt++) {
            int cn = wn * 32 + nt * 8 + qid * 2;
            if (cn < 112) {
                float bb0 = b3S[cn], bb1 = b3S[cn + 1];
                h3S[r * 116 + cn]           = fmaxf(acc3[mt][nt][0] + bb0, 0.f);
                h3S[r * 116 + cn + 1]       = fmaxf(acc3[mt][nt][1] + bb1, 0.f);
                h3S[(r + 8) * 116 + cn]     = fmaxf(acc3[mt][nt][2] + bb0, 0.f);
                h3S[(r + 8) * 116 + cn + 1] = fmaxf(acc3[mt][nt][3] + bb1, 0.f);
            }
        }
    }
    __syncthreads();

    // ---- layer4 (scalar): pred = h3 @ W4 + b4 ----
    {
        int m = tid >> 2;
        int q = tid & 3;
        if (q < 3) {
            int os = q * 2;
            float pr[2] = {b4S[os], b4S[os + 1]};
#pragma unroll 4
            for (int k = 0; k < 112; k++) {
                float h = h3S[m * 116 + k];
                pr[0] += h * w4S[k * 8 + os];
                pr[1] += h * w4S[k * 8 + os + 1];
            }
            if (m < M) {
                int s = sid[m];
                g_pred[s * 6 + os]     = pr[0];
                g_pred[s * 6 + os + 1] = pr[1];
            }
        }
    }
}

__global__ void k_scatter(const float* __restrict__ x, float* __restrict__ out) {
    int s = blockIdx.x * blockDim.x + threadIdx.x;
    if (s >= BB) return;
    size_t base = (size_t)s * XX;
#pragma unroll
    for (int j = 0; j < 6; j++) {
        int id = g_idx[s * 6 + j];
        out[base + id] = x[base + id] + g_pred[s * 6 + j];
    }
}

extern "C" void kernel_launch(void* const* d_in, const int* in_sizes, int n_in,
                              void* d_out, int out_size) {
    const float* x  = (const float*)d_in[0];
    const float* W1 = (const float*)d_in[1];
    const float* b1 = (const float*)d_in[2];
    const float* W2 = (const float*)d_in[3];
    const float* b2 = (const float*)d_in[4];
    const float* W3 = (const float*)d_in[5];
    const float* b3 = (const float*)d_in[6];
    const float* W4 = (const float*)d_in[7];
    const float* b4 = (const float*)d_in[8];
    const int*  act = (const int*)d_in[9];
    float* out = (float*)d_out;

    cudaFuncSetAttribute(k_mlp, cudaFuncAttributeMaxDynamicSharedMemorySize, SMEM_BYTES);

    k_reset<<<1, 32>>>();
    k_prepw<<<12, 256>>>(W2, W3);
    k_prep<<<BB / 8, 256>>>(x, act, out);
    dim3 g2((BB + TM - 1) / TM, 3);
    k_mlp<<<g2, 512, SMEM_BYTES>>>(W1, b1, b2, b3, W4, b4);
    k_scatter<<<BB / 256, 256>>>(x, out);
}

// round 6
// speedup vs baseline: 1.4934x; 1.4934x over previous
#include <cuda_runtime.h>
#include <cuda_bf16.h>
#include <cuda_fp16.h>
#include <cstdint>

#define BB 65536
#define XX 362
#define GS 19
#define TM 128

// ---- weight image (per action,chunk): B2 [128n][120k] fp16, B3 [128n][136k] fp16 ----
#define IMG_B2 0
#define IMG_B2_BYTES 30720
#define IMG_B3 30720
#define IMG_B3_BYTES 34816
#define IMGSZ 65536

// ---- smem layout (bytes) ----
#define OFF_WBUF 0
#define OFF_H1   34816
#define OFF_H2   65536
#define OFF_ATT  100352
#define OFF_W1   104448
#define OFF_B1   106848
#define OFF_B2   107248
#define OFF_B3   109296
#define OFF_W4   109744
#define OFF_B4   113328
#define OFF_SID  113360
#define SMEM_BYTES 113872

// ---- device scratch ----
__device__ float g_att[BB * 6];
__device__ int   g_idx[BB * 6];
__device__ int   g_list[3][BB];
__device__ int   g_count[3];
__device__ __align__(16) unsigned char g_wimg[12 * IMGSZ];

__device__ __forceinline__ uint32_t packh2(float e, float o) {
    __half2 t = __floats2half2_rn(e, o);
    return *reinterpret_cast<uint32_t*>(&t);
}
__device__ __forceinline__ void mma16816(float* c, const uint32_t* a, uint32_t b0, uint32_t b1) {
    asm volatile("mma.sync.aligned.m16n8k16.row.col.f32.f16.f16.f32 "
                 "{%0,%1,%2,%3}, {%4,%5,%6,%7}, {%8,%9}, {%0,%1,%2,%3};"
                 : "+f"(c[0]), "+f"(c[1]), "+f"(c[2]), "+f"(c[3])
                 : "r"(a[0]), "r"(a[1]), "r"(a[2]), "r"(a[3]), "r"(b0), "r"(b1));
}

// ================= small kernels =================
__global__ void k_reset() {
    if (threadIdx.x < 3) g_count[threadIdx.x] = 0;
}

// Pre-convert W2^T / W3^T to fp16 padded [N][K] images.
__global__ void k_prepw(const float* __restrict__ W2, const float* __restrict__ W3) {
    int img = blockIdx.x;           // a*4 + c
    int a = img >> 2, c = img & 3;
    unsigned char* base = g_wimg + (size_t)img * IMGSZ;
    __half* b2h = (__half*)(base + IMG_B2);
    __half* b3h = (__half*)(base + IMG_B3);
    for (int p = threadIdx.x; p < 128 * 120; p += blockDim.x) {
        int n = p / 120, k = p % 120;
        int gn = c * 128 + n;
        float v = (k < 100 && gn < 400) ? W2[(a * 100 + k) * 400 + gn] : 0.f;
        b2h[p] = __float2half_rn(v);
    }
    for (int p = threadIdx.x; p < 128 * 136; p += blockDim.x) {
        int n = p / 136, k = p % 136;
        int gk = c * 128 + k;
        float v = (n < 100 && k < 128 && gk < 400) ? W3[(a * 400 + gk) * 100 + n] : 0.f;
        b3h[p] = __float2half_rn(v);
    }
}

// One warp per sample: argmax, row copy, gather att, bucket by action.
__global__ void k_prep(const float* __restrict__ x, const int* __restrict__ act,
                       float* __restrict__ out) {
    int s = (blockIdx.x * blockDim.x + threadIdx.x) >> 5;
    int lane = threadIdx.x & 31;
    if (s >= BB) return;
    const float* row = x + (size_t)s * XX;
    float* orow = out + (size_t)s * XX;

    float best = -3.4e38f;
    int bidx = XX;
    for (int i = lane; i < XX; i += 32) {
        float v = row[i];
        orow[i] = v;
        if (v > best) { best = v; bidx = i; }
    }
#pragma unroll
    for (int off = 16; off; off >>= 1) {
        float ov = __shfl_down_sync(0xffffffffu, best, off);
        int oi = __shfl_down_sync(0xffffffffu, bidx, off);
        if (ov > best || (ov == best && oi < bidx)) { best = ov; bidx = oi; }
    }
    bidx = __shfl_sync(0xffffffffu, bidx, 0);

    if (lane < 6) {
        int id;
        if (lane == 0) id = 0;
        else if (lane == 1) id = bidx;
        else {
            int d = (lane == 2) ? -GS : (lane == 3) ? GS : (lane == 4) ? -1 : 1;
            id = bidx + d;
            id = id < 1 ? 1 : (id > XX - 1 ? XX - 1 : id);
        }
        g_idx[s * 6 + lane] = id;
        g_att[s * 6 + lane] = row[id];
    }
    if (lane == 0) {
        int a = act[s];
        int pos = atomicAdd(&g_count[a], 1);
        g_list[a][pos] = s;
    }
}

// ================= fp16 mma.sync MLP (512 threads, 4x4 warp grid) + fused scatter =================
__global__ __launch_bounds__(512)
void k_mlp(const float* __restrict__ W1, const float* __restrict__ b1,
           const float* __restrict__ b2, const float* __restrict__ b3,
           const float* __restrict__ W4, const float* __restrict__ b4,
           float* __restrict__ out) {
    extern __shared__ char sm[];
    int a = blockIdx.y;
    int count = g_count[a];
    int m0 = blockIdx.x * TM;
    if (m0 >= count) return;
    int M = min(TM, count - m0);
    int tid = threadIdx.x;
    int wid = tid >> 5, lane = tid & 31;
    int grp = lane >> 2, qid = lane & 3;
    int wm = wid >> 2, wn = wid & 3;

    int*   sid  = (int*)(sm + OFF_SID);
    float* attS = (float*)(sm + OFF_ATT);
    float* w1S  = (float*)(sm + OFF_W1);
    float* b1S  = (float*)(sm + OFF_B1);
    float* b2S  = (float*)(sm + OFF_B2);
    float* b3S  = (float*)(sm + OFF_B3);
    float* w4S  = (float*)(sm + OFF_W4);
    float* b4S  = (float*)(sm + OFF_B4);

    uint32_t* wbH = (uint32_t*)(sm + OFF_WBUF);      // B2: stride 60 words; B3: stride 68
    uint32_t* h1H = (uint32_t*)(sm + OFF_H1);        // [128][60w] fp16x2
    uint32_t* h2H = (uint32_t*)(sm + OFF_H2);        // [128][68w] fp16x2

    // ---- stage misc ----
    if (tid < TM) sid[tid] = (tid < M) ? g_list[a][m0 + tid] : 0;
    for (int p = tid; p < 600; p += 512) w1S[p] = W1[a * 600 + p];
    if (tid < 100) b1S[tid] = b1[a * 100 + tid];
    if (tid < 512) b2S[tid] = (tid < 400) ? b2[a * 400 + tid] : 0.f;
    if (tid < 112) b3S[tid] = (tid < 100) ? b3[a * 100 + tid] : 0.f;
    for (int p = tid; p < 896; p += 512) {
        int k = p >> 3, o = p & 7;
        w4S[p] = (k < 100 && o < 6) ? W4[(a * 100 + k) * 6 + o] : 0.f;
    }
    if (tid < 8) b4S[tid] = (tid < 6) ? b4[a * 6 + tid] : 0.f;
    __syncthreads();
    for (int p = tid; p < 1024; p += 512) {
        int m = p >> 3, q = p & 7;
        attS[p] = (m < M && q < 6) ? g_att[sid[m] * 6 + q] : 0.f;
    }
    __syncthreads();

    // ---- layer1 (scalar): h1 = relu(att@W1+b1) -> fp16, cols 0..111 (pad 0) ----
    {
        int m = tid >> 2;
        int i0 = (tid & 3) * 30;
        float at[6];
#pragma unroll
        for (int q = 0; q < 6; q++) at[q] = attS[m * 8 + q];
        __half* hh = (__half*)h1H;
#pragma unroll 5
        for (int ii = 0; ii < 30; ii++) {
            int i = i0 + ii;
            float v = 0.f;
            if (i < 100) {
                v = b1S[i];
#pragma unroll
                for (int q = 0; q < 6; q++) v += at[q] * w1S[q * 100 + i];
                v = fmaxf(v, 0.f);
            }
            hh[m * 120 + i] = __float2half_rn(v);
        }
    }

    const unsigned char* img = g_wimg + (size_t)(a * 4) * IMGSZ;
    float acc3[2][4][4];
#pragma unroll
    for (int mt = 0; mt < 2; mt++)
#pragma unroll
        for (int nt = 0; nt < 4; nt++)
#pragma unroll
            for (int e = 0; e < 4; e++) acc3[mt][nt][e] = 0.f;

    for (int c = 0; c < 4; c++) {
        __syncthreads();   // h1 ready (c=0) / prev chunk readers done
        {   // stage W2 chunk
            const uint4* src = (const uint4*)(img + (size_t)c * IMGSZ + IMG_B2);
            uint4* dst = (uint4*)(sm + OFF_WBUF);
            for (int p = tid; p < IMG_B2_BYTES / 16; p += 512) dst[p] = src[p];
        }
        __syncthreads();

        // ---- layer2 chunk: C[128x128] = h1 @ W2c, warp tile 32x32, single fp16 pass ----
        float acc2[2][4][4];
#pragma unroll
        for (int mt = 0; mt < 2; mt++)
#pragma unroll
            for (int nt = 0; nt < 4; nt++)
#pragma unroll
                for (int e = 0; e < 4; e++) acc2[mt][nt][e] = 0.f;

#pragma unroll
        for (int kk = 0; kk < 7; kk++) {
            uint32_t af[2][4];
#pragma unroll
            for (int mt = 0; mt < 2; mt++) {
                int r = wm * 32 + mt * 16 + grp;
                af[mt][0] = h1H[r * 60 + kk * 8 + qid];
                af[mt][1] = h1H[(r + 8) * 60 + kk * 8 + qid];
                af[mt][2] = h1H[r * 60 + kk * 8 + 4 + qid];
                af[mt][3] = h1H[(r + 8) * 60 + kk * 8 + 4 + qid];
            }
#pragma unroll
            for (int nt = 0; nt < 4; nt++) {
                int n = wn * 32 + nt * 8 + grp;
                uint32_t b0 = wbH[n * 60 + kk * 8 + qid];
                uint32_t bq = wbH[n * 60 + kk * 8 + 4 + qid];
                mma16816(acc2[0][nt], af[0], b0, bq);
                mma16816(acc2[1][nt], af[1], b0, bq);
            }
        }
        // epilogue: h2 = relu(C + b2) -> fp16
#pragma unroll
        for (int mt = 0; mt < 2; mt++) {
            int r = wm * 32 + mt * 16 + grp;
#pragma unroll
            for (int nt = 0; nt < 4; nt++) {
                int cn = wn * 32 + nt * 8 + qid * 2;
                float bb0 = b2S[c * 128 + cn], bb1 = b2S[c * 128 + cn + 1];
                float v00 = fmaxf(acc2[mt][nt][0] + bb0, 0.f);
                float v01 = fmaxf(acc2[mt][nt][1] + bb1, 0.f);
                float v10 = fmaxf(acc2[mt][nt][2] + bb0, 0.f);
                float v11 = fmaxf(acc2[mt][nt][3] + bb1, 0.f);
                h2H[r * 68 + cn / 2]       = packh2(v00, v01);
                h2H[(r + 8) * 68 + cn / 2] = packh2(v10, v11);
            }
        }
        __syncthreads();   // all h2 written, W buffer reads done
        {   // stage W3 chunk
            const uint4* src = (const uint4*)(img + (size_t)c * IMGSZ + IMG_B3);
            uint4* dst = (uint4*)(sm + OFF_WBUF);
            for (int p = tid; p < IMG_B3_BYTES / 16; p += 512) dst[p] = src[p];
        }
        __syncthreads();

        // ---- layer3 partial: acc3 += h2c @ W3c (N rows 112..127 zero pad) ----
#pragma unroll
        for (int kk = 0; kk < 8; kk++) {
            uint32_t af[2][4];
#pragma unroll
            for (int mt = 0; mt < 2; mt++) {
                int r = wm * 32 + mt * 16 + grp;
                af[mt][0] = h2H[r * 68 + kk * 8 + qid];
                af[mt][1] = h2H[(r + 8) * 68 + kk * 8 + qid];
                af[mt][2] = h2H[r * 68 + kk * 8 + 4 + qid];
                af[mt][3] = h2H[(r + 8) * 68 + kk * 8 + 4 + qid];
            }
#pragma unroll
            for (int nt = 0; nt < 4; nt++) {
                int n = wn * 32 + nt * 8 + grp;
                uint32_t b0 = wbH[n * 68 + kk * 8 + qid];
                uint32_t bq = wbH[n * 68 + kk * 8 + 4 + qid];
                mma16816(acc3[0][nt], af[0], b0, bq);
                mma16816(acc3[1][nt], af[1], b0, bq);
            }
        }
    }
    __syncthreads();   // W3/h1 regions dead -> reuse [0, 65536) as h3 fp32

    // ---- epilogue3: h3 = relu(acc3 + b3) -> fp32 smem [128][116], cols < 112 ----
    float* h3S = (float*)(sm + OFF_WBUF);
#pragma unroll
    for (int mt = 0; mt < 2; mt++) {
        int r = wm * 32 + mt * 16 + grp;
#pragma unroll
        for (int nt = 0; nt < 4; nt++) {
            int cn = wn * 32 + nt * 8 + qid * 2;
            if (cn < 112) {
                float bb0 = b3S[cn], bb1 = b3S[cn + 1];
                h3S[r * 116 + cn]           = fmaxf(acc3[mt][nt][0] + bb0, 0.f);
                h3S[r * 116 + cn + 1]       = fmaxf(acc3[mt][nt][1] + bb1, 0.f);
                h3S[(r + 8) * 116 + cn]     = fmaxf(acc3[mt][nt][2] + bb0, 0.f);
                h3S[(r + 8) * 116 + cn + 1] = fmaxf(acc3[mt][nt][3] + bb1, 0.f);
            }
        }
    }
    __syncthreads();

    // ---- layer4 (scalar): pred = h3 @ W4 + b4 -> predS ----
    float* predS = (float*)(sm + OFF_H2);   // [128][6]
    {
        int m = tid >> 2;
        int q = tid & 3;
        if (q < 3) {
            int os = q * 2;
            float pr[2] = {b4S[os], b4S[os + 1]};
#pragma unroll 4
            for (int k = 0; k < 112; k++) {
                float h = h3S[m * 116 + k];
                pr[0] += h * w4S[k * 8 + os];
                pr[1] += h * w4S[k * 8 + os + 1];
            }
            predS[m * 6 + os]     = pr[0];
            predS[m * 6 + os + 1] = pr[1];
        }
    }
    __syncthreads();

    // ---- fused scatter: out[s][idx_j] = x[s][idx_j] + pred[j], j ascending (last wins) ----
    if (tid < M) {
        int s = sid[tid];
        size_t base = (size_t)s * XX;
#pragma unroll
        for (int j = 0; j < 6; j++) {
            int id = g_idx[s * 6 + j];
            out[base + id] = g_att[s * 6 + j] + predS[tid * 6 + j];
        }
    }
}

extern "C" void kernel_launch(void* const* d_in, const int* in_sizes, int n_in,
                              void* d_out, int out_size) {
    const float* x  = (const float*)d_in[0];
    const float* W1 = (const float*)d_in[1];
    const float* b1 = (const float*)d_in[2];
    const float* W2 = (const float*)d_in[3];
    const float* b2 = (const float*)d_in[4];
    const float* W3 = (const float*)d_in[5];
    const float* b3 = (const float*)d_in[6];
    const float* W4 = (const float*)d_in[7];
    const float* b4 = (const float*)d_in[8];
    const int*  act = (const int*)d_in[9];
    float* out = (float*)d_out;

    cudaFuncSetAttribute(k_mlp, cudaFuncAttributeMaxDynamicSharedMemorySize, SMEM_BYTES);

    k_reset<<<1, 32>>>();
    k_prepw<<<12, 256>>>(W2, W3);
    k_prep<<<BB / 8, 256>>>(x, act, out);
    dim3 g2((BB + TM - 1) / TM, 3);
    k_mlp<<<g2, 512, SMEM_BYTES>>>(W1, b1, b2, b3, W4, b4, out);
}